// round 8
// baseline (speedup 1.0000x reference)
#include <cuda_runtime.h>
#include <math.h>

// Problem constants (fixed by the dataset)
#define N_NODES 30000
#define E_EDGES 480000
#define E_TOT   (E_EDGES + N_NODES)   // edges + self loops = 510000
#define G_GRAPHS 128
#define MAXF 192
#define SCAN_B 1024
#define SCAN_NB ((N_NODES + SCAN_B - 1) / SCAN_B)

typedef unsigned long long ull;

// ---------------- scratch (static device globals; no allocation) -------------
__device__ float g_x   [N_NODES * MAXF];
__device__ float g_xl  [N_NODES * MAXF];
__device__ float g_xr  [N_NODES * MAXF];
__device__ float g_p   [E_TOT * 3];       // fallback prob buffer (deg > CAP)
__device__ int   g_deg [N_NODES];
__device__ int   g_rp  [N_NODES + 1];
__device__ int   g_cur [N_NODES];
__device__ int   g_csrc[E_TOT];
__device__ int   g_part[SCAN_NB];
__device__ float g_gs  [G_GRAPHS * 64];
__device__ float g_cnt [G_GRAPHS];

// ---------------- f32x2 helpers ------------------------------------------------
__device__ __forceinline__ ull pack2(float lo, float hi) {
    ull r; asm("mov.b64 %0, {%1, %2};" : "=l"(r) : "f"(lo), "f"(hi)); return r;
}
__device__ __forceinline__ void fma2(ull& acc, ull a, ull b) {
    asm("fma.rn.f32x2 %0, %1, %2, %3;" : "=l"(acc) : "l"(a), "l"(b), "l"(acc));
}

// ---------------- small utility kernels ----------------------------------------
__global__ void k_fill_f(float* __restrict__ p, float v, int n) {
    int i = blockIdx.x * blockDim.x + threadIdx.x;
    if (i < n) p[i] = v;
}
__global__ void k_fill_i(int* __restrict__ p, int v, int n) {
    int i = blockIdx.x * blockDim.x + threadIdx.x;
    if (i < n) p[i] = v;
}

// ---------------- CSR build (by destination) -----------------------------------
__global__ void k_count(const int* __restrict__ ei, int* __restrict__ deg) {
    int e = blockIdx.x * blockDim.x + threadIdx.x;
    if (e >= E_TOT) return;
    int dst = (e < E_EDGES) ? ei[E_EDGES + e] : (e - E_EDGES);
    atomicAdd(&deg[dst], 1);
}

__global__ void k_scan1(const int* __restrict__ deg, int* __restrict__ part) {
    __shared__ int sm[SCAN_B];
    int i = blockIdx.x * SCAN_B + threadIdx.x;
    sm[threadIdx.x] = (i < N_NODES) ? deg[i] : 0;
    __syncthreads();
    for (int o = SCAN_B / 2; o; o >>= 1) {
        if (threadIdx.x < o) sm[threadIdx.x] += sm[threadIdx.x + o];
        __syncthreads();
    }
    if (threadIdx.x == 0) part[blockIdx.x] = sm[0];
}
__global__ void k_scan2(int* __restrict__ part) {
    int run = 0;
    for (int b = 0; b < SCAN_NB; b++) { int v = part[b]; part[b] = run; run += v; }
}
__global__ void k_scan3(const int* __restrict__ deg, const int* __restrict__ part,
                        int* __restrict__ rp, int* __restrict__ cur) {
    __shared__ int sm[SCAN_B];
    int i = blockIdx.x * SCAN_B + threadIdx.x;
    int v = (i < N_NODES) ? deg[i] : 0;
    sm[threadIdx.x] = v;
    __syncthreads();
    for (int o = 1; o < SCAN_B; o <<= 1) {
        int t = (threadIdx.x >= o) ? sm[threadIdx.x - o] : 0;
        __syncthreads();
        sm[threadIdx.x] += t;
        __syncthreads();
    }
    int excl = sm[threadIdx.x] - v + part[blockIdx.x];
    if (i < N_NODES) { rp[i] = excl; cur[i] = excl; }
    if (i == N_NODES - 1) rp[N_NODES] = excl + v;
}

__global__ void k_scatter(const int* __restrict__ ei, int* __restrict__ cur,
                          int* __restrict__ csrc) {
    int e = blockIdx.x * blockDim.x + threadIdx.x;
    if (e >= E_TOT) return;
    int src, dst;
    if (e < E_EDGES) { src = ei[e]; dst = ei[E_EDGES + e]; }
    else             { src = dst = e - E_EDGES; }
    int pos = atomicAdd(&cur[dst], 1);
    csrc[pos] = src;
}

// ---------------- row-tiled dual GEMM with packed f32x2 FMA ---------------------
// block = M threads, ROWS rows per block, X tile transposed in smem.
// EMB: gather input rows through ids (embedding lookup fused into layer 0).
template <int K, int M, int ROWS, bool EMB>
__global__ void k_gemm2(const float* __restrict__ X, const int* __restrict__ ids,
                        const float* __restrict__ Wl, const float* __restrict__ bl,
                        const float* __restrict__ Wr, const float* __restrict__ br,
                        float* __restrict__ Yl, float* __restrict__ Yr) {
    constexpr int PAD = ROWS + 2;
    constexpr int NP  = ROWS / 2;
    __shared__ __align__(16) float sxt[K * PAD];
    int row0 = blockIdx.x * ROWS;
    int nr = min(ROWS, N_NODES - row0);
    for (int i = threadIdx.x; i < nr * K; i += M) {
        int r = i / K, k = i - r * K;
        float v = EMB ? X[(size_t)ids[row0 + r] * K + k]
                      : X[(size_t)row0 * K + i];
        sxt[k * PAD + r] = v;
    }
    for (int i = threadIdx.x; i < (ROWS - nr) * K; i += M) {
        int r = nr + i / K, k = i - (i / K) * K;
        sxt[k * PAD + r] = 0.0f;
    }
    __syncthreads();

    int c = threadIdx.x;
    ull al[NP], ar[NP];
    {
        ull bl2 = pack2(bl[c], bl[c]);
        ull br2 = pack2(br[c], br[c]);
        #pragma unroll
        for (int p = 0; p < NP; p++) { al[p] = bl2; ar[p] = br2; }
    }
    #pragma unroll 4
    for (int k = 0; k < K; k++) {
        float wl = Wl[k * M + c], wr = Wr[k * M + c];
        ull wl2 = pack2(wl, wl), wr2 = pack2(wr, wr);
        const float* rowp = &sxt[k * PAD];
        #pragma unroll
        for (int p = 0; p < NP; p++) {
            ull xv = *(const ull*)(rowp + 2 * p);
            fma2(al[p], xv, wl2);
            fma2(ar[p], xv, wr2);
        }
    }
    #pragma unroll
    for (int p = 0; p < NP; p++) {
        float2 ul = *(float2*)&al[p];
        float2 ur = *(float2*)&ar[p];
        int r0 = 2 * p;
        if (r0 < nr) {
            Yl[(size_t)(row0 + r0) * M + c] = ul.x;
            Yr[(size_t)(row0 + r0) * M + c] = ur.x;
        }
        if (r0 + 1 < nr) {
            Yl[(size_t)(row0 + r0 + 1) * M + c] = ul.y;
            Yr[(size_t)(row0 + r0 + 1) * M + c] = ur.y;
        }
    }
}

// ---------------- fused attention + aggregation (block per dst node) ------------
// xl rows fetched ONCE from L2 in phase 1 and cached in smem (CAPX rows);
// phase 3 aggregates from shared memory. Deterministic fallbacks for overflow.
template <int H, int C, int TBL, int CAPX>
__global__ void k_attn(const float* __restrict__ xl, const float* __restrict__ xr,
                       const float* __restrict__ att, const float* __restrict__ bo,
                       const int* __restrict__ rp, const int* __restrict__ csrc,
                       float* __restrict__ gp, float* __restrict__ out) {
    constexpr int M   = H * C;
    constexpr int CAP = 256;          // prob/src smem capacity
    __shared__ float s_xr[M], s_att[M];
    __shared__ float s_m[H], s_den[H], s_inv[H];
    __shared__ int   s_src[CAP];
    __shared__ float s_p[CAP * H];
    __shared__ float s_xl[CAPX * M];

    int dst = blockIdx.x;
    int tid = threadIdx.x;
    int start = rp[dst];
    int deg   = rp[dst + 1] - start;
    bool fits = (deg <= CAP);
    float* pb = fits ? s_p : (gp + (size_t)start * H);
    const int* srcp = fits ? s_src : (csrc + start);

    for (int j = tid; j < M; j += TBL) {
        s_xr[j] = xr[(size_t)dst * M + j];
        s_att[j] = att[j];
    }
    if (tid < H) { s_m[tid] = -INFINITY; s_den[tid] = 0.f; }
    if (fits) for (int i = tid; i < deg; i += TBL) s_src[i] = csrc[start + i];
    __syncthreads();

    // phase 1: logits (warp per edge) + stash xl row into smem cache
    int wid = tid >> 5, lane = tid & 31;
    constexpr int NW = TBL / 32;
    for (int e = wid; e < deg; e += NW) {
        const float* xls = xl + (size_t)srcp[e] * M;
        bool cache = (e < CAPX);
        #pragma unroll
        for (int h = 0; h < H; h++) {
            float s = 0.f;
            #pragma unroll
            for (int c = lane; c < C; c += 32) {
                int j = h * C + c;
                float xv = xls[j];
                if (cache) s_xl[e * M + j] = xv;
                float v = xv + s_xr[j];
                v = (v > 0.f) ? v : 0.2f * v;
                s = fmaf(s_att[j], v, s);
            }
            #pragma unroll
            for (int o = 16; o; o >>= 1) s += __shfl_xor_sync(0xffffffffu, s, o);
            if (lane == 0) {
                pb[e * H + h] = s;
                int* a = (int*)&s_m[h];
                int old = *a;
                while (__int_as_float(old) < s) {
                    int assumed = old;
                    old = atomicCAS(a, assumed, __float_as_int(s));
                    if (old == assumed) break;
                }
            }
        }
    }
    __syncthreads();

    // phase 2: exp + denominator, then scale probs -> alpha in place
    for (int i = tid; i < deg * H; i += TBL) {
        int h = i % H;
        float v = expf(pb[i] - s_m[h]);
        pb[i] = v;
        atomicAdd(&s_den[h], v);
    }
    __syncthreads();
    if (tid < H) s_inv[tid] = 1.0f / s_den[tid];
    __syncthreads();
    for (int i = tid; i < deg * H; i += TBL) pb[i] *= s_inv[i % H];
    __syncthreads();

    // phase 3: one thread per output column, aggregate from smem cache
    if (tid < M) {
        int j = tid;
        int h = j / C;
        float acc = 0.f;
        int ncache = min(deg, CAPX);
        int e = 0;
        for (; e + 1 < ncache; e += 2) {
            float a0 = pb[e * H + h],       x0 = s_xl[e * M + j];
            float a1 = pb[(e + 1) * H + h], x1 = s_xl[(e + 1) * M + j];
            acc = fmaf(a0, x0, acc);
            acc = fmaf(a1, x1, acc);
        }
        for (; e < ncache; e++) acc = fmaf(pb[e * H + h], s_xl[e * M + j], acc);
        for (e = ncache; e < deg; e++)      // overflow rows: global fallback
            acc = fmaf(pb[e * H + h], xl[(size_t)srcp[e] * M + j], acc);
        out[(size_t)dst * M + j] = acc + bo[j];
    }
}

// ---------------- pooling (sorted batch -> run-length local sums) ---------------
__global__ void k_pool2(const float* __restrict__ x, const int* __restrict__ batch,
                        float* __restrict__ gs, float* __restrict__ cnt) {
    int j = threadIdx.x;              // 0..63 feature
    int w = threadIdx.y;              // 0..3
    int i0 = blockIdx.x * 128;
    int iend = min(i0 + 128, N_NODES);
    float acc = 0.f, cn = 0.f;
    int curb = -1;
    for (int i = i0 + w; i < iend; i += 4) {
        int b = batch[i];
        if (b != curb) {
            if (curb >= 0) {
                atomicAdd(&gs[curb * 64 + j], acc);
                if (j == 0) atomicAdd(&cnt[curb], cn);
            }
            curb = b; acc = 0.f; cn = 0.f;
        }
        acc += x[(size_t)i * 64 + j];
        cn += 1.f;
    }
    if (curb >= 0) {
        atomicAdd(&gs[curb * 64 + j], acc);
        if (j == 0) atomicAdd(&cnt[curb], cn);
    }
}

__global__ void k_mlp(const float* __restrict__ gs, const float* __restrict__ cnt,
                      const float* __restrict__ demo,
                      const float* __restrict__ Wc1, const float* __restrict__ bc1,
                      const float* __restrict__ Wc2, const float* __restrict__ bc2,
                      float* __restrict__ out) {
    int g = blockIdx.x * blockDim.x + threadIdx.x;
    if (g >= G_GRAPHS) return;
    float inv = 1.0f / fmaxf(cnt[g], 1.0f);
    float in[69];
    #pragma unroll
    for (int j = 0; j < 64; j++) in[j] = gs[g * 64 + j] * inv;
    #pragma unroll
    for (int j = 0; j < 5; j++) in[64 + j] = demo[g * 5 + j];
    float h[32];
    #pragma unroll
    for (int o = 0; o < 32; o++) {
        float a = bc1[o];
        for (int i = 0; i < 69; i++) a = fmaf(in[i], Wc1[i * 32 + o], a);
        h[o] = fmaxf(a, 0.0f);
    }
    #pragma unroll
    for (int o = 0; o < 2; o++) {
        float a = bc2[o];
        #pragma unroll
        for (int i = 0; i < 32; i++) a = fmaf(h[i], Wc2[i * 2 + o], a);
        out[g * 2 + o] = a;
    }
}

// ---------------- launch --------------------------------------------------------
static inline int ceil_div(int a, int b) { return (a + b - 1) / b; }

extern "C" void kernel_launch(void* const* d_in, const int* in_sizes, int n_in,
                              void* d_out, int out_size) {
    const float* emb  = (const float*)d_in[0];
    const float* Wl0  = (const float*)d_in[1];
    const float* bl0  = (const float*)d_in[2];
    const float* Wr0  = (const float*)d_in[3];
    const float* br0  = (const float*)d_in[4];
    const float* att0 = (const float*)d_in[5];
    const float* bo0  = (const float*)d_in[6];
    const float* Wl1  = (const float*)d_in[7];
    const float* bl1  = (const float*)d_in[8];
    const float* Wr1  = (const float*)d_in[9];
    const float* br1  = (const float*)d_in[10];
    const float* att1 = (const float*)d_in[11];
    const float* bo1  = (const float*)d_in[12];
    const float* Wl2  = (const float*)d_in[13];
    const float* bl2  = (const float*)d_in[14];
    const float* Wr2  = (const float*)d_in[15];
    const float* br2  = (const float*)d_in[16];
    const float* att2 = (const float*)d_in[17];
    const float* bo2  = (const float*)d_in[18];
    const float* Wc1  = (const float*)d_in[19];
    const float* bc1  = (const float*)d_in[20];
    const float* Wc2  = (const float*)d_in[21];
    const float* bc2  = (const float*)d_in[22];
    const float* demo = (const float*)d_in[23];
    const int*   ids  = (const int*)d_in[24];
    const int*   ei   = (const int*)d_in[25];
    const int*   batch= (const int*)d_in[26];
    float* out = (float*)d_out;

    float *px, *pxl, *pxr, *pp, *pgs, *pcnt;
    int *pdeg, *prp, *pcur, *pcsrc, *ppart;
    cudaGetSymbolAddress((void**)&px,    g_x);
    cudaGetSymbolAddress((void**)&pxl,   g_xl);
    cudaGetSymbolAddress((void**)&pxr,   g_xr);
    cudaGetSymbolAddress((void**)&pp,    g_p);
    cudaGetSymbolAddress((void**)&pdeg,  g_deg);
    cudaGetSymbolAddress((void**)&prp,   g_rp);
    cudaGetSymbolAddress((void**)&pcur,  g_cur);
    cudaGetSymbolAddress((void**)&pcsrc, g_csrc);
    cudaGetSymbolAddress((void**)&ppart, g_part);
    cudaGetSymbolAddress((void**)&pgs,   g_gs);
    cudaGetSymbolAddress((void**)&pcnt,  g_cnt);

    const int T = 256;

    // CSR by destination (shared by all three layers)
    k_fill_i<<<ceil_div(N_NODES, T), T>>>(pdeg, 0, N_NODES);
    k_count<<<ceil_div(E_TOT, T), T>>>(ei, pdeg);
    k_scan1<<<SCAN_NB, SCAN_B>>>(pdeg, ppart);
    k_scan2<<<1, 1>>>(ppart);
    k_scan3<<<SCAN_NB, SCAN_B>>>(pdeg, ppart, prp, pcur);
    k_scatter<<<ceil_div(E_TOT, T), T>>>(ei, pcur, pcsrc);

    // layer 0: emb-gathered 16 -> 3 heads x 32   (embedding lookup fused)
    k_gemm2<16, 96, 32, true><<<ceil_div(N_NODES, 32), 96>>>(emb, ids, Wl0, bl0, Wr0, br0, pxl, pxr);
    k_attn<3, 32, 96, 64><<<N_NODES, 96>>>(pxl, pxr, att0, bo0, prp, pcsrc, pp, px);

    // layer 1: 96 -> 2 heads x 96
    k_gemm2<96, 192, 32, false><<<ceil_div(N_NODES, 32), 192>>>(px, nullptr, Wl1, bl1, Wr1, br1, pxl, pxr);
    k_attn<2, 96, 192, 48><<<N_NODES, 192>>>(pxl, pxr, att1, bo1, prp, pcsrc, pp, px);

    // layer 2: 192 -> 1 head x 64
    k_gemm2<192, 64, 32, false><<<ceil_div(N_NODES, 32), 64>>>(px, nullptr, Wl2, bl2, Wr2, br2, pxl, pxr);
    k_attn<1, 64, 128, 64><<<N_NODES, 128>>>(pxl, pxr, att2, bo2, prp, pcsrc, pp, px);

    // global mean pool + MLP head
    k_fill_f<<<ceil_div(G_GRAPHS * 64, T), T>>>(pgs, 0.0f, G_GRAPHS * 64);
    k_fill_f<<<1, G_GRAPHS>>>(pcnt, 0.0f, G_GRAPHS);
    dim3 pb(64, 4);
    k_pool2<<<ceil_div(N_NODES, 128), pb>>>(px, batch, pgs, pcnt);
    k_mlp<<<1, G_GRAPHS>>>(pgs, pcnt, demo, Wc1, bc1, Wc2, bc2, out);
}

// round 10
// speedup vs baseline: 1.4706x; 1.4706x over previous
#include <cuda_runtime.h>
#include <math.h>

// Problem constants (fixed by the dataset)
#define N_NODES 30000
#define E_EDGES 480000
#define E_TOT   (E_EDGES + N_NODES)   // edges + self loops = 510000
#define G_GRAPHS 128
#define MAXF 192
#define TB 128                        // threads per block in attention kernel
#define SCAN_B 1024
#define SCAN_NB ((N_NODES + SCAN_B - 1) / SCAN_B)

typedef unsigned long long ull;

// ---------------- scratch (static device globals; no allocation) -------------
__device__ float g_x   [N_NODES * MAXF];
__device__ float g_xl  [N_NODES * MAXF];
__device__ float g_xr  [N_NODES * MAXF];
__device__ float g_p   [E_TOT * 3];       // fallback prob buffer (deg > CAP)
__device__ int   g_deg [N_NODES];
__device__ int   g_rp  [N_NODES + 1];
__device__ int   g_cur [N_NODES];
__device__ int   g_csrc[E_TOT];
__device__ int   g_part[SCAN_NB];
__device__ float g_gs  [G_GRAPHS * 64];
__device__ float g_cnt [G_GRAPHS];

// ---------------- f32x2 helpers ------------------------------------------------
__device__ __forceinline__ ull pack2(float lo, float hi) {
    ull r; asm("mov.b64 %0, {%1, %2};" : "=l"(r) : "f"(lo), "f"(hi)); return r;
}
__device__ __forceinline__ void fma2(ull& acc, ull a, ull b) {
    asm("fma.rn.f32x2 %0, %1, %2, %3;" : "=l"(acc) : "l"(a), "l"(b), "l"(acc));
}

// ---------------- small utility kernels ----------------------------------------
__global__ void k_fill_f(float* __restrict__ p, float v, int n) {
    int i = blockIdx.x * blockDim.x + threadIdx.x;
    if (i < n) p[i] = v;
}
__global__ void k_fill_i(int* __restrict__ p, int v, int n) {
    int i = blockIdx.x * blockDim.x + threadIdx.x;
    if (i < n) p[i] = v;
}

// ---------------- CSR build (by destination) -----------------------------------
__global__ void k_count(const int* __restrict__ ei, int* __restrict__ deg) {
    int e = blockIdx.x * blockDim.x + threadIdx.x;
    if (e >= E_TOT) return;
    int dst = (e < E_EDGES) ? ei[E_EDGES + e] : (e - E_EDGES);
    atomicAdd(&deg[dst], 1);
}

__global__ void k_scan1(const int* __restrict__ deg, int* __restrict__ part) {
    __shared__ int sm[SCAN_B];
    int i = blockIdx.x * SCAN_B + threadIdx.x;
    sm[threadIdx.x] = (i < N_NODES) ? deg[i] : 0;
    __syncthreads();
    for (int o = SCAN_B / 2; o; o >>= 1) {
        if (threadIdx.x < o) sm[threadIdx.x] += sm[threadIdx.x + o];
        __syncthreads();
    }
    if (threadIdx.x == 0) part[blockIdx.x] = sm[0];
}
__global__ void k_scan2(int* __restrict__ part) {
    int run = 0;
    for (int b = 0; b < SCAN_NB; b++) { int v = part[b]; part[b] = run; run += v; }
}
__global__ void k_scan3(const int* __restrict__ deg, const int* __restrict__ part,
                        int* __restrict__ rp, int* __restrict__ cur) {
    __shared__ int sm[SCAN_B];
    int i = blockIdx.x * SCAN_B + threadIdx.x;
    int v = (i < N_NODES) ? deg[i] : 0;
    sm[threadIdx.x] = v;
    __syncthreads();
    for (int o = 1; o < SCAN_B; o <<= 1) {
        int t = (threadIdx.x >= o) ? sm[threadIdx.x - o] : 0;
        __syncthreads();
        sm[threadIdx.x] += t;
        __syncthreads();
    }
    int excl = sm[threadIdx.x] - v + part[blockIdx.x];
    if (i < N_NODES) { rp[i] = excl; cur[i] = excl; }
    if (i == N_NODES - 1) rp[N_NODES] = excl + v;
}

__global__ void k_scatter(const int* __restrict__ ei, int* __restrict__ cur,
                          int* __restrict__ csrc) {
    int e = blockIdx.x * blockDim.x + threadIdx.x;
    if (e >= E_TOT) return;
    int src, dst;
    if (e < E_EDGES) { src = ei[e]; dst = ei[E_EDGES + e]; }
    else             { src = dst = e - E_EDGES; }
    int pos = atomicAdd(&cur[dst], 1);
    csrc[pos] = src;
}

// ---------------- row-tiled dual GEMM with packed f32x2 FMA ---------------------
// block = M threads, ROWS rows per block, X tile transposed in smem.
// EMB: gather input rows through ids (embedding lookup fused into layer 0).
template <int K, int M, int ROWS, bool EMB>
__global__ void k_gemm2(const float* __restrict__ X, const int* __restrict__ ids,
                        const float* __restrict__ Wl, const float* __restrict__ bl,
                        const float* __restrict__ Wr, const float* __restrict__ br,
                        float* __restrict__ Yl, float* __restrict__ Yr) {
    constexpr int PAD = ROWS + 2;
    constexpr int NP  = ROWS / 2;
    __shared__ __align__(16) float sxt[K * PAD];
    int row0 = blockIdx.x * ROWS;
    int nr = min(ROWS, N_NODES - row0);
    for (int i = threadIdx.x; i < nr * K; i += M) {
        int r = i / K, k = i - r * K;
        float v = EMB ? X[(size_t)ids[row0 + r] * K + k]
                      : X[(size_t)row0 * K + i];
        sxt[k * PAD + r] = v;
    }
    for (int i = threadIdx.x; i < (ROWS - nr) * K; i += M) {
        int r = nr + i / K, k = i - (i / K) * K;
        sxt[k * PAD + r] = 0.0f;
    }
    __syncthreads();

    int c = threadIdx.x;
    ull al[NP], ar[NP];
    {
        ull bl2 = pack2(bl[c], bl[c]);
        ull br2 = pack2(br[c], br[c]);
        #pragma unroll
        for (int p = 0; p < NP; p++) { al[p] = bl2; ar[p] = br2; }
    }
    #pragma unroll 4
    for (int k = 0; k < K; k++) {
        float wl = Wl[k * M + c], wr = Wr[k * M + c];
        ull wl2 = pack2(wl, wl), wr2 = pack2(wr, wr);
        const float* rowp = &sxt[k * PAD];
        #pragma unroll
        for (int p = 0; p < NP; p++) {
            ull xv = *(const ull*)(rowp + 2 * p);
            fma2(al[p], xv, wl2);
            fma2(ar[p], xv, wr2);
        }
    }
    #pragma unroll
    for (int p = 0; p < NP; p++) {
        float2 ul = *(float2*)&al[p];
        float2 ur = *(float2*)&ar[p];
        int r0 = 2 * p;
        if (r0 < nr) {
            Yl[(size_t)(row0 + r0) * M + c] = ul.x;
            Yr[(size_t)(row0 + r0) * M + c] = ur.x;
        }
        if (r0 + 1 < nr) {
            Yl[(size_t)(row0 + r0 + 1) * M + c] = ul.y;
            Yr[(size_t)(row0 + r0 + 1) * M + c] = ur.y;
        }
    }
}

// ---------------- fused attention + aggregation (block per dst node) ------------
// R7 structure (high occupancy, small smem); denominator folded into epilogue.
template <int H, int C>
__global__ void k_attn(const float* __restrict__ xl, const float* __restrict__ xr,
                       const float* __restrict__ att, const float* __restrict__ bo,
                       const int* __restrict__ rp, const int* __restrict__ csrc,
                       float* __restrict__ gp, float* __restrict__ out) {
    constexpr int M   = H * C;
    constexpr int CAP = 256;
    constexpr int Q   = (M + TB - 1) / TB;
    __shared__ float s_xr[M], s_att[M];
    __shared__ float s_m[H], s_den[H], s_inv[H];
    __shared__ int   s_src[CAP];
    __shared__ float s_p[CAP * H];

    int dst = blockIdx.x;
    int tid = threadIdx.x;
    int start = rp[dst];
    int deg   = rp[dst + 1] - start;
    bool fits = (deg <= CAP);
    float* pb = fits ? s_p : (gp + (size_t)start * H);
    const int* srcp = fits ? s_src : (csrc + start);

    for (int j = tid; j < M; j += TB) {
        s_xr[j] = xr[(size_t)dst * M + j];
        s_att[j] = att[j];
    }
    if (tid < H) { s_m[tid] = -INFINITY; s_den[tid] = 0.f; }
    if (fits) for (int i = tid; i < deg; i += TB) s_src[i] = csrc[start + i];
    __syncthreads();

    // phase 1: logits (warp per edge), block max per head via shared CAS
    int wid = tid >> 5, lane = tid & 31;
    for (int e = wid; e < deg; e += TB / 32) {
        const float* xls = xl + (size_t)srcp[e] * M;
        #pragma unroll
        for (int h = 0; h < H; h++) {
            float s = 0.f;
            #pragma unroll
            for (int c = lane; c < C; c += 32) {
                int j = h * C + c;
                float v = xls[j] + s_xr[j];
                v = (v > 0.f) ? v : 0.2f * v;
                s = fmaf(s_att[j], v, s);
            }
            #pragma unroll
            for (int o = 16; o; o >>= 1) s += __shfl_xor_sync(0xffffffffu, s, o);
            if (lane == 0) {
                pb[e * H + h] = s;
                int* a = (int*)&s_m[h];
                int old = *a;
                while (__int_as_float(old) < s) {
                    int assumed = old;
                    old = atomicCAS(a, assumed, __float_as_int(s));
                    if (old == assumed) break;
                }
            }
        }
    }
    __syncthreads();

    // phase 2: exp + denominator (no normalization pass — folded into epilogue)
    for (int i = tid; i < deg * H; i += TB) {
        int h = i % H;
        float v = expf(pb[i] - s_m[h]);
        pb[i] = v;
        atomicAdd(&s_den[h], v);
    }
    __syncthreads();
    if (tid < H) s_inv[tid] = 1.0f / s_den[tid];
    __syncthreads();

    // phase 3: p-weighted gather-aggregate; scale by 1/den once at the end
    float acc[Q];
    int hq[Q];
    #pragma unroll
    for (int q = 0; q < Q; q++) { acc[q] = 0.f; hq[q] = (tid + q * TB) / C; }
    #pragma unroll 2
    for (int e = 0; e < deg; e++) {
        const float* xls = xl + (size_t)srcp[e] * M;
        #pragma unroll
        for (int q = 0; q < Q; q++) {
            int j = tid + q * TB;
            if (j < M) acc[q] = fmaf(pb[e * H + hq[q]], xls[j], acc[q]);
        }
    }
    #pragma unroll
    for (int q = 0; q < Q; q++) {
        int j = tid + q * TB;
        if (j < M) out[(size_t)dst * M + j] = fmaf(acc[q], s_inv[hq[q]], bo[j]);
    }
}

// ---------------- pooling (sorted batch -> run-length local sums) ---------------
__global__ void k_pool2(const float* __restrict__ x, const int* __restrict__ batch,
                        float* __restrict__ gs, float* __restrict__ cnt) {
    int j = threadIdx.x;              // 0..63 feature
    int w = threadIdx.y;              // 0..3
    int i0 = blockIdx.x * 128;
    int iend = min(i0 + 128, N_NODES);
    float acc = 0.f, cn = 0.f;
    int curb = -1;
    for (int i = i0 + w; i < iend; i += 4) {
        int b = batch[i];
        if (b != curb) {
            if (curb >= 0) {
                atomicAdd(&gs[curb * 64 + j], acc);
                if (j == 0) atomicAdd(&cnt[curb], cn);
            }
            curb = b; acc = 0.f; cn = 0.f;
        }
        acc += x[(size_t)i * 64 + j];
        cn += 1.f;
    }
    if (curb >= 0) {
        atomicAdd(&gs[curb * 64 + j], acc);
        if (j == 0) atomicAdd(&cnt[curb], cn);
    }
}

__global__ void k_mlp(const float* __restrict__ gs, const float* __restrict__ cnt,
                      const float* __restrict__ demo,
                      const float* __restrict__ Wc1, const float* __restrict__ bc1,
                      const float* __restrict__ Wc2, const float* __restrict__ bc2,
                      float* __restrict__ out) {
    int g = blockIdx.x * blockDim.x + threadIdx.x;
    if (g >= G_GRAPHS) return;
    float inv = 1.0f / fmaxf(cnt[g], 1.0f);
    float in[69];
    #pragma unroll
    for (int j = 0; j < 64; j++) in[j] = gs[g * 64 + j] * inv;
    #pragma unroll
    for (int j = 0; j < 5; j++) in[64 + j] = demo[g * 5 + j];
    float h[32];
    #pragma unroll
    for (int o = 0; o < 32; o++) {
        float a = bc1[o];
        for (int i = 0; i < 69; i++) a = fmaf(in[i], Wc1[i * 32 + o], a);
        h[o] = fmaxf(a, 0.0f);
    }
    #pragma unroll
    for (int o = 0; o < 2; o++) {
        float a = bc2[o];
        #pragma unroll
        for (int i = 0; i < 32; i++) a = fmaf(h[i], Wc2[i * 2 + o], a);
        out[g * 2 + o] = a;
    }
}

// ---------------- launch --------------------------------------------------------
static inline int ceil_div(int a, int b) { return (a + b - 1) / b; }

extern "C" void kernel_launch(void* const* d_in, const int* in_sizes, int n_in,
                              void* d_out, int out_size) {
    const float* emb  = (const float*)d_in[0];
    const float* Wl0  = (const float*)d_in[1];
    const float* bl0  = (const float*)d_in[2];
    const float* Wr0  = (const float*)d_in[3];
    const float* br0  = (const float*)d_in[4];
    const float* att0 = (const float*)d_in[5];
    const float* bo0  = (const float*)d_in[6];
    const float* Wl1  = (const float*)d_in[7];
    const float* bl1  = (const float*)d_in[8];
    const float* Wr1  = (const float*)d_in[9];
    const float* br1  = (const float*)d_in[10];
    const float* att1 = (const float*)d_in[11];
    const float* bo1  = (const float*)d_in[12];
    const float* Wl2  = (const float*)d_in[13];
    const float* bl2  = (const float*)d_in[14];
    const float* Wr2  = (const float*)d_in[15];
    const float* br2  = (const float*)d_in[16];
    const float* att2 = (const float*)d_in[17];
    const float* bo2  = (const float*)d_in[18];
    const float* Wc1  = (const float*)d_in[19];
    const float* bc1  = (const float*)d_in[20];
    const float* Wc2  = (const float*)d_in[21];
    const float* bc2  = (const float*)d_in[22];
    const float* demo = (const float*)d_in[23];
    const int*   ids  = (const int*)d_in[24];
    const int*   ei   = (const int*)d_in[25];
    const int*   batch= (const int*)d_in[26];
    float* out = (float*)d_out;

    float *px, *pxl, *pxr, *pp, *pgs, *pcnt;
    int *pdeg, *prp, *pcur, *pcsrc, *ppart;
    cudaGetSymbolAddress((void**)&px,    g_x);
    cudaGetSymbolAddress((void**)&pxl,   g_xl);
    cudaGetSymbolAddress((void**)&pxr,   g_xr);
    cudaGetSymbolAddress((void**)&pp,    g_p);
    cudaGetSymbolAddress((void**)&pdeg,  g_deg);
    cudaGetSymbolAddress((void**)&prp,   g_rp);
    cudaGetSymbolAddress((void**)&pcur,  g_cur);
    cudaGetSymbolAddress((void**)&pcsrc, g_csrc);
    cudaGetSymbolAddress((void**)&ppart, g_part);
    cudaGetSymbolAddress((void**)&pgs,   g_gs);
    cudaGetSymbolAddress((void**)&pcnt,  g_cnt);

    const int T = 256;

    // CSR by destination (shared by all three layers)
    k_fill_i<<<ceil_div(N_NODES, T), T>>>(pdeg, 0, N_NODES);
    k_count<<<ceil_div(E_TOT, T), T>>>(ei, pdeg);
    k_scan1<<<SCAN_NB, SCAN_B>>>(pdeg, ppart);
    k_scan2<<<1, 1>>>(ppart);
    k_scan3<<<SCAN_NB, SCAN_B>>>(pdeg, ppart, prp, pcur);
    k_scatter<<<ceil_div(E_TOT, T), T>>>(ei, pcur, pcsrc);

    // layer 0: emb-gathered 16 -> 3 heads x 32   (embedding lookup fused)
    k_gemm2<16, 96, 32, true><<<ceil_div(N_NODES, 32), 96>>>(emb, ids, Wl0, bl0, Wr0, br0, pxl, pxr);
    k_attn<3, 32><<<N_NODES, TB>>>(pxl, pxr, att0, bo0, prp, pcsrc, pp, px);

    // layer 1: 96 -> 2 heads x 96
    k_gemm2<96, 192, 32, false><<<ceil_div(N_NODES, 32), 192>>>(px, nullptr, Wl1, bl1, Wr1, br1, pxl, pxr);
    k_attn<2, 96><<<N_NODES, TB>>>(pxl, pxr, att1, bo1, prp, pcsrc, pp, px);

    // layer 2: 192 -> 1 head x 64
    k_gemm2<192, 64, 32, false><<<ceil_div(N_NODES, 32), 64>>>(px, nullptr, Wl2, bl2, Wr2, br2, pxl, pxr);
    k_attn<1, 64><<<N_NODES, TB>>>(pxl, pxr, att2, bo2, prp, pcsrc, pp, px);

    // global mean pool + MLP head
    k_fill_f<<<ceil_div(G_GRAPHS * 64, T), T>>>(pgs, 0.0f, G_GRAPHS * 64);
    k_fill_f<<<1, G_GRAPHS>>>(pcnt, 0.0f, G_GRAPHS);
    dim3 pb(64, 4);
    k_pool2<<<ceil_div(N_NODES, 128), pb>>>(px, batch, pgs, pcnt);
    k_mlp<<<1, G_GRAPHS>>>(pgs, pcnt, demo, Wc1, bc1, Wc2, bc2, out);
}

// round 11
// speedup vs baseline: 1.8531x; 1.2601x over previous
#include <cuda_runtime.h>
#include <math.h>

// Problem constants (fixed by the dataset)
#define N_NODES 30000
#define E_EDGES 480000
#define E_TOT   (E_EDGES + N_NODES)   // edges + self loops = 510000
#define G_GRAPHS 128
#define MAXF 192
#define TB 128                        // threads per block in attention kernel
#define SCAN_B 1024
#define SCAN_NB ((N_NODES + SCAN_B - 1) / SCAN_B)

typedef unsigned long long ull;

// ---------------- scratch (static device globals; no allocation) -------------
__device__ float g_x   [N_NODES * MAXF];
__device__ float g_xl  [N_NODES * MAXF];
__device__ float g_xr  [N_NODES * MAXF];
__device__ int   g_deg [N_NODES];
__device__ int   g_rp  [N_NODES + 1];
__device__ int   g_cur [N_NODES];
__device__ int   g_csrc[E_TOT];
__device__ int   g_part[SCAN_NB];
__device__ float g_gs  [G_GRAPHS * 64];
__device__ float g_cnt [G_GRAPHS];

// ---------------- f32x2 helpers ------------------------------------------------
__device__ __forceinline__ ull pack2(float lo, float hi) {
    ull r; asm("mov.b64 %0, {%1, %2};" : "=l"(r) : "f"(lo), "f"(hi)); return r;
}
__device__ __forceinline__ void fma2(ull& acc, ull a, ull b) {
    asm("fma.rn.f32x2 %0, %1, %2, %3;" : "=l"(acc) : "l"(a), "l"(b), "l"(acc));
}

// ---------------- small utility kernels ----------------------------------------
__global__ void k_fill_f(float* __restrict__ p, float v, int n) {
    int i = blockIdx.x * blockDim.x + threadIdx.x;
    if (i < n) p[i] = v;
}
__global__ void k_fill_i(int* __restrict__ p, int v, int n) {
    int i = blockIdx.x * blockDim.x + threadIdx.x;
    if (i < n) p[i] = v;
}

// ---------------- CSR build (by destination) -----------------------------------
__global__ void k_count(const int* __restrict__ ei, int* __restrict__ deg) {
    int e = blockIdx.x * blockDim.x + threadIdx.x;
    if (e >= E_TOT) return;
    int dst = (e < E_EDGES) ? ei[E_EDGES + e] : (e - E_EDGES);
    atomicAdd(&deg[dst], 1);
}

__global__ void k_scan1(const int* __restrict__ deg, int* __restrict__ part) {
    __shared__ int sm[SCAN_B];
    int i = blockIdx.x * SCAN_B + threadIdx.x;
    sm[threadIdx.x] = (i < N_NODES) ? deg[i] : 0;
    __syncthreads();
    for (int o = SCAN_B / 2; o; o >>= 1) {
        if (threadIdx.x < o) sm[threadIdx.x] += sm[threadIdx.x + o];
        __syncthreads();
    }
    if (threadIdx.x == 0) part[blockIdx.x] = sm[0];
}
__global__ void k_scan2(int* __restrict__ part) {
    int run = 0;
    for (int b = 0; b < SCAN_NB; b++) { int v = part[b]; part[b] = run; run += v; }
}
__global__ void k_scan3(const int* __restrict__ deg, const int* __restrict__ part,
                        int* __restrict__ rp, int* __restrict__ cur) {
    __shared__ int sm[SCAN_B];
    int i = blockIdx.x * SCAN_B + threadIdx.x;
    int v = (i < N_NODES) ? deg[i] : 0;
    sm[threadIdx.x] = v;
    __syncthreads();
    for (int o = 1; o < SCAN_B; o <<= 1) {
        int t = (threadIdx.x >= o) ? sm[threadIdx.x - o] : 0;
        __syncthreads();
        sm[threadIdx.x] += t;
        __syncthreads();
    }
    int excl = sm[threadIdx.x] - v + part[blockIdx.x];
    if (i < N_NODES) { rp[i] = excl; cur[i] = excl; }
    if (i == N_NODES - 1) rp[N_NODES] = excl + v;
}

__global__ void k_scatter(const int* __restrict__ ei, int* __restrict__ cur,
                          int* __restrict__ csrc) {
    int e = blockIdx.x * blockDim.x + threadIdx.x;
    if (e >= E_TOT) return;
    int src, dst;
    if (e < E_EDGES) { src = ei[e]; dst = ei[E_EDGES + e]; }
    else             { src = dst = e - E_EDGES; }
    int pos = atomicAdd(&cur[dst], 1);
    csrc[pos] = src;
}

// ---------------- row-tiled dual GEMM with packed f32x2 FMA ---------------------
template <int K, int M, int ROWS, bool EMB>
__global__ void k_gemm2(const float* __restrict__ X, const int* __restrict__ ids,
                        const float* __restrict__ Wl, const float* __restrict__ bl,
                        const float* __restrict__ Wr, const float* __restrict__ br,
                        float* __restrict__ Yl, float* __restrict__ Yr) {
    constexpr int PAD = ROWS + 2;
    constexpr int NP  = ROWS / 2;
    __shared__ __align__(16) float sxt[K * PAD];
    int row0 = blockIdx.x * ROWS;
    int nr = min(ROWS, N_NODES - row0);
    for (int i = threadIdx.x; i < nr * K; i += M) {
        int r = i / K, k = i - r * K;
        float v = EMB ? X[(size_t)ids[row0 + r] * K + k]
                      : X[(size_t)row0 * K + i];
        sxt[k * PAD + r] = v;
    }
    for (int i = threadIdx.x; i < (ROWS - nr) * K; i += M) {
        int r = nr + i / K, k = i - (i / K) * K;
        sxt[k * PAD + r] = 0.0f;
    }
    __syncthreads();

    int c = threadIdx.x;
    ull al[NP], ar[NP];
    {
        ull bl2 = pack2(bl[c], bl[c]);
        ull br2 = pack2(br[c], br[c]);
        #pragma unroll
        for (int p = 0; p < NP; p++) { al[p] = bl2; ar[p] = br2; }
    }
    #pragma unroll 4
    for (int k = 0; k < K; k++) {
        float wl = Wl[k * M + c], wr = Wr[k * M + c];
        ull wl2 = pack2(wl, wl), wr2 = pack2(wr, wr);
        const float* rowp = &sxt[k * PAD];
        #pragma unroll
        for (int p = 0; p < NP; p++) {
            ull xv = *(const ull*)(rowp + 2 * p);
            fma2(al[p], xv, wl2);
            fma2(ar[p], xv, wr2);
        }
    }
    #pragma unroll
    for (int p = 0; p < NP; p++) {
        float2 ul = *(float2*)&al[p];
        float2 ur = *(float2*)&ar[p];
        int r0 = 2 * p;
        if (r0 < nr) {
            Yl[(size_t)(row0 + r0) * M + c] = ul.x;
            Yr[(size_t)(row0 + r0) * M + c] = ur.x;
        }
        if (r0 + 1 < nr) {
            Yl[(size_t)(row0 + r0 + 1) * M + c] = ul.y;
            Yr[(size_t)(row0 + r0 + 1) * M + c] = ur.y;
        }
    }
}

// ---------------- single-pass fused attention (online softmax) ------------------
// Block per dst node. Edges processed in CHUNK-sized groups:
//   stage xl rows -> smem while computing logits (one global read per row),
//   H state-threads update running max/denominator + per-edge exp weights,
//   all threads rescale accumulators and fold the chunk in.
// Works for any degree; no global scratch, no atomics.
template <int H, int C, int CHUNK>
__global__ void k_attn(const float* __restrict__ xl, const float* __restrict__ xr,
                       const float* __restrict__ att, const float* __restrict__ bo,
                       const int* __restrict__ rp, const int* __restrict__ csrc,
                       float* __restrict__ out) {
    constexpr int M  = H * C;
    constexpr int Q  = (M + TB - 1) / TB;
    constexpr int NW = TB / 32;
    __shared__ float s_xr[M], s_att[M];
    __shared__ float s_chunk[CHUNK * M];
    __shared__ float s_logit[CHUNK * H];
    __shared__ float s_pe[CHUNK * H];
    __shared__ float s_scale[H];
    __shared__ float s_m[H], s_den[H];

    int dst = blockIdx.x;
    int tid = threadIdx.x;
    int start = rp[dst];
    int deg   = rp[dst + 1] - start;

    for (int j = tid; j < M; j += TB) {
        s_xr[j] = xr[(size_t)dst * M + j];
        s_att[j] = att[j];
    }
    if (tid < H) { s_m[tid] = -INFINITY; s_den[tid] = 0.f; }

    float acc[Q];
    int jq[Q], hq[Q];
    #pragma unroll
    for (int q = 0; q < Q; q++) {
        jq[q] = tid + q * TB;
        hq[q] = (jq[q] < M) ? jq[q] / C : 0;
        acc[q] = 0.f;
    }
    __syncthreads();

    int wid = tid >> 5, lane = tid & 31;
    for (int base = 0; base < deg; base += CHUNK) {
        int n = min(CHUNK, deg - base);

        // stage xl rows into smem and compute logits from the same values
        for (int e = wid; e < n; e += NW) {
            const float* row = xl + (size_t)csrc[start + base + e] * M;
            #pragma unroll
            for (int h = 0; h < H; h++) {
                float s = 0.f;
                #pragma unroll
                for (int c = lane; c < C; c += 32) {
                    int j = h * C + c;
                    float v = row[j];
                    s_chunk[e * M + j] = v;
                    float u = v + s_xr[j];
                    u = (u > 0.f) ? u : 0.2f * u;
                    s = fmaf(s_att[j], u, s);
                }
                #pragma unroll
                for (int o = 16; o; o >>= 1) s += __shfl_xor_sync(0xffffffffu, s, o);
                if (lane == 0) s_logit[e * H + h] = s;
            }
        }
        __syncthreads();

        // softmax state update (one thread per head)
        if (tid < H) {
            float m_old = s_m[tid];
            float mc = m_old;
            for (int e = 0; e < n; e++) mc = fmaxf(mc, s_logit[e * H + tid]);
            float sc = __expf(m_old - mc);
            float d = s_den[tid] * sc;
            for (int e = 0; e < n; e++) {
                float pe = __expf(s_logit[e * H + tid] - mc);
                s_pe[e * H + tid] = pe;
                d += pe;
            }
            s_scale[tid] = sc;
            s_den[tid] = d;
            s_m[tid] = mc;
        }
        __syncthreads();

        // accumulate chunk
        #pragma unroll
        for (int q = 0; q < Q; q++) {
            if (jq[q] < M) {
                float a = acc[q] * s_scale[hq[q]];
                for (int e = 0; e < n; e++)
                    a = fmaf(s_pe[e * H + hq[q]], s_chunk[e * M + jq[q]], a);
                acc[q] = a;
            }
        }
        __syncthreads();   // protect s_chunk/s_logit/s_pe before next chunk
    }

    #pragma unroll
    for (int q = 0; q < Q; q++) {
        if (jq[q] < M)
            out[(size_t)dst * M + jq[q]] = __fdividef(acc[q], s_den[hq[q]]) + bo[jq[q]];
    }
}

// ---------------- pooling (sorted batch -> run-length local sums) ---------------
__global__ void k_pool2(const float* __restrict__ x, const int* __restrict__ batch,
                        float* __restrict__ gs, float* __restrict__ cnt) {
    int j = threadIdx.x;              // 0..63 feature
    int w = threadIdx.y;              // 0..3
    int i0 = blockIdx.x * 128;
    int iend = min(i0 + 128, N_NODES);
    float acc = 0.f, cn = 0.f;
    int curb = -1;
    for (int i = i0 + w; i < iend; i += 4) {
        int b = batch[i];
        if (b != curb) {
            if (curb >= 0) {
                atomicAdd(&gs[curb * 64 + j], acc);
                if (j == 0) atomicAdd(&cnt[curb], cn);
            }
            curb = b; acc = 0.f; cn = 0.f;
        }
        acc += x[(size_t)i * 64 + j];
        cn += 1.f;
    }
    if (curb >= 0) {
        atomicAdd(&gs[curb * 64 + j], acc);
        if (j == 0) atomicAdd(&cnt[curb], cn);
    }
}

__global__ void k_mlp(const float* __restrict__ gs, const float* __restrict__ cnt,
                      const float* __restrict__ demo,
                      const float* __restrict__ Wc1, const float* __restrict__ bc1,
                      const float* __restrict__ Wc2, const float* __restrict__ bc2,
                      float* __restrict__ out) {
    int g = blockIdx.x * blockDim.x + threadIdx.x;
    if (g >= G_GRAPHS) return;
    float inv = 1.0f / fmaxf(cnt[g], 1.0f);
    float in[69];
    #pragma unroll
    for (int j = 0; j < 64; j++) in[j] = gs[g * 64 + j] * inv;
    #pragma unroll
    for (int j = 0; j < 5; j++) in[64 + j] = demo[g * 5 + j];
    float h[32];
    #pragma unroll
    for (int o = 0; o < 32; o++) {
        float a = bc1[o];
        for (int i = 0; i < 69; i++) a = fmaf(in[i], Wc1[i * 32 + o], a);
        h[o] = fmaxf(a, 0.0f);
    }
    #pragma unroll
    for (int o = 0; o < 2; o++) {
        float a = bc2[o];
        #pragma unroll
        for (int i = 0; i < 32; i++) a = fmaf(h[i], Wc2[i * 2 + o], a);
        out[g * 2 + o] = a;
    }
}

// ---------------- launch --------------------------------------------------------
static inline int ceil_div(int a, int b) { return (a + b - 1) / b; }

extern "C" void kernel_launch(void* const* d_in, const int* in_sizes, int n_in,
                              void* d_out, int out_size) {
    const float* emb  = (const float*)d_in[0];
    const float* Wl0  = (const float*)d_in[1];
    const float* bl0  = (const float*)d_in[2];
    const float* Wr0  = (const float*)d_in[3];
    const float* br0  = (const float*)d_in[4];
    const float* att0 = (const float*)d_in[5];
    const float* bo0  = (const float*)d_in[6];
    const float* Wl1  = (const float*)d_in[7];
    const float* bl1  = (const float*)d_in[8];
    const float* Wr1  = (const float*)d_in[9];
    const float* br1  = (const float*)d_in[10];
    const float* att1 = (const float*)d_in[11];
    const float* bo1  = (const float*)d_in[12];
    const float* Wl2  = (const float*)d_in[13];
    const float* bl2  = (const float*)d_in[14];
    const float* Wr2  = (const float*)d_in[15];
    const float* br2  = (const float*)d_in[16];
    const float* att2 = (const float*)d_in[17];
    const float* bo2  = (const float*)d_in[18];
    const float* Wc1  = (const float*)d_in[19];
    const float* bc1  = (const float*)d_in[20];
    const float* Wc2  = (const float*)d_in[21];
    const float* bc2  = (const float*)d_in[22];
    const float* demo = (const float*)d_in[23];
    const int*   ids  = (const int*)d_in[24];
    const int*   ei   = (const int*)d_in[25];
    const int*   batch= (const int*)d_in[26];
    float* out = (float*)d_out;

    float *px, *pxl, *pxr, *pgs, *pcnt;
    int *pdeg, *prp, *pcur, *pcsrc, *ppart;
    cudaGetSymbolAddress((void**)&px,    g_x);
    cudaGetSymbolAddress((void**)&pxl,   g_xl);
    cudaGetSymbolAddress((void**)&pxr,   g_xr);
    cudaGetSymbolAddress((void**)&pdeg,  g_deg);
    cudaGetSymbolAddress((void**)&prp,   g_rp);
    cudaGetSymbolAddress((void**)&pcur,  g_cur);
    cudaGetSymbolAddress((void**)&pcsrc, g_csrc);
    cudaGetSymbolAddress((void**)&ppart, g_part);
    cudaGetSymbolAddress((void**)&pgs,   g_gs);
    cudaGetSymbolAddress((void**)&pcnt,  g_cnt);

    const int T = 256;

    // CSR by destination (shared by all three layers)
    k_fill_i<<<ceil_div(N_NODES, T), T>>>(pdeg, 0, N_NODES);
    k_count<<<ceil_div(E_TOT, T), T>>>(ei, pdeg);
    k_scan1<<<SCAN_NB, SCAN_B>>>(pdeg, ppart);
    k_scan2<<<1, 1>>>(ppart);
    k_scan3<<<SCAN_NB, SCAN_B>>>(pdeg, ppart, prp, pcur);
    k_scatter<<<ceil_div(E_TOT, T), T>>>(ei, pcur, pcsrc);

    // layer 0: emb-gathered 16 -> 3 heads x 32   (embedding lookup fused)
    k_gemm2<16, 96, 32, true><<<ceil_div(N_NODES, 32), 96>>>(emb, ids, Wl0, bl0, Wr0, br0, pxl, pxr);
    k_attn<3, 32, 8><<<N_NODES, TB>>>(pxl, pxr, att0, bo0, prp, pcsrc, px);

    // layer 1: 96 -> 2 heads x 96
    k_gemm2<96, 192, 32, false><<<ceil_div(N_NODES, 32), 192>>>(px, nullptr, Wl1, bl1, Wr1, br1, pxl, pxr);
    k_attn<2, 96, 8><<<N_NODES, TB>>>(pxl, pxr, att1, bo1, prp, pcsrc, px);

    // layer 2: 192 -> 1 head x 64
    k_gemm2<192, 64, 32, false><<<ceil_div(N_NODES, 32), 64>>>(px, nullptr, Wl2, bl2, Wr2, br2, pxl, pxr);
    k_attn<1, 64, 8><<<N_NODES, TB>>>(pxl, pxr, att2, bo2, prp, pcsrc, px);

    // global mean pool + MLP head
    k_fill_f<<<ceil_div(G_GRAPHS * 64, T), T>>>(pgs, 0.0f, G_GRAPHS * 64);
    k_fill_f<<<1, G_GRAPHS>>>(pcnt, 0.0f, G_GRAPHS);
    dim3 pb(64, 4);
    k_pool2<<<ceil_div(N_NODES, 128), pb>>>(px, batch, pgs, pcnt);
    k_mlp<<<1, G_GRAPHS>>>(pgs, pcnt, demo, Wc1, bc1, Wc2, bc2, out);
}

// round 12
// speedup vs baseline: 2.7304x; 1.4734x over previous
#include <cuda_runtime.h>
#include <math.h>

// Problem constants (fixed by the dataset)
#define N_NODES 30000
#define E_EDGES 480000
#define E_TOT   (E_EDGES + N_NODES)   // edges + self loops = 510000
#define G_GRAPHS 128
#define MAXF 192
#define SCAN_B 1024
#define SCAN_NB ((N_NODES + SCAN_B - 1) / SCAN_B)

typedef unsigned long long ull;

// ---------------- scratch (static device globals; no allocation) -------------
__device__ float g_x   [N_NODES * MAXF];
__device__ float g_xl  [N_NODES * MAXF];
__device__ float g_xr  [N_NODES * MAXF];
__device__ int   g_deg [N_NODES];
__device__ int   g_rp  [N_NODES + 1];
__device__ int   g_cur [N_NODES];
__device__ int   g_csrc[E_TOT];
__device__ int   g_part[SCAN_NB];
__device__ float g_gs  [G_GRAPHS * 64];
__device__ float g_cnt [G_GRAPHS];

// ---------------- f32x2 helpers ------------------------------------------------
__device__ __forceinline__ ull pack2(float lo, float hi) {
    ull r; asm("mov.b64 %0, {%1, %2};" : "=l"(r) : "f"(lo), "f"(hi)); return r;
}
__device__ __forceinline__ void fma2(ull& acc, ull a, ull b) {
    asm("fma.rn.f32x2 %0, %1, %2, %3;" : "=l"(acc) : "l"(a), "l"(b), "l"(acc));
}

// ---------------- small utility kernels ----------------------------------------
__global__ void k_fill_f(float* __restrict__ p, float v, int n) {
    int i = blockIdx.x * blockDim.x + threadIdx.x;
    if (i < n) p[i] = v;
}
__global__ void k_fill_i(int* __restrict__ p, int v, int n) {
    int i = blockIdx.x * blockDim.x + threadIdx.x;
    if (i < n) p[i] = v;
}

// ---------------- CSR build (by destination) -----------------------------------
__global__ void k_count(const int* __restrict__ ei, int* __restrict__ deg) {
    int e = blockIdx.x * blockDim.x + threadIdx.x;
    if (e >= E_TOT) return;
    int dst = (e < E_EDGES) ? ei[E_EDGES + e] : (e - E_EDGES);
    atomicAdd(&deg[dst], 1);
}

__global__ void k_scan1(const int* __restrict__ deg, int* __restrict__ part) {
    __shared__ int sm[SCAN_B];
    int i = blockIdx.x * SCAN_B + threadIdx.x;
    sm[threadIdx.x] = (i < N_NODES) ? deg[i] : 0;
    __syncthreads();
    for (int o = SCAN_B / 2; o; o >>= 1) {
        if (threadIdx.x < o) sm[threadIdx.x] += sm[threadIdx.x + o];
        __syncthreads();
    }
    if (threadIdx.x == 0) part[blockIdx.x] = sm[0];
}
__global__ void k_scan2(int* __restrict__ part) {
    int run = 0;
    for (int b = 0; b < SCAN_NB; b++) { int v = part[b]; part[b] = run; run += v; }
}
__global__ void k_scan3(const int* __restrict__ deg, const int* __restrict__ part,
                        int* __restrict__ rp, int* __restrict__ cur) {
    __shared__ int sm[SCAN_B];
    int i = blockIdx.x * SCAN_B + threadIdx.x;
    int v = (i < N_NODES) ? deg[i] : 0;
    sm[threadIdx.x] = v;
    __syncthreads();
    for (int o = 1; o < SCAN_B; o <<= 1) {
        int t = (threadIdx.x >= o) ? sm[threadIdx.x - o] : 0;
        __syncthreads();
        sm[threadIdx.x] += t;
        __syncthreads();
    }
    int excl = sm[threadIdx.x] - v + part[blockIdx.x];
    if (i < N_NODES) { rp[i] = excl; cur[i] = excl; }
    if (i == N_NODES - 1) rp[N_NODES] = excl + v;
}

__global__ void k_scatter(const int* __restrict__ ei, int* __restrict__ cur,
                          int* __restrict__ csrc) {
    int e = blockIdx.x * blockDim.x + threadIdx.x;
    if (e >= E_TOT) return;
    int src, dst;
    if (e < E_EDGES) { src = ei[e]; dst = ei[E_EDGES + e]; }
    else             { src = dst = e - E_EDGES; }
    int pos = atomicAdd(&cur[dst], 1);
    csrc[pos] = src;
}

// ---------------- row-tiled dual GEMM with packed f32x2 FMA ---------------------
template <int K, int M, int ROWS, bool EMB>
__global__ void k_gemm2(const float* __restrict__ X, const int* __restrict__ ids,
                        const float* __restrict__ Wl, const float* __restrict__ bl,
                        const float* __restrict__ Wr, const float* __restrict__ br,
                        float* __restrict__ Yl, float* __restrict__ Yr) {
    constexpr int PAD = ROWS + 2;
    constexpr int NP  = ROWS / 2;
    __shared__ __align__(16) float sxt[K * PAD];
    int row0 = blockIdx.x * ROWS;
    int nr = min(ROWS, N_NODES - row0);
    for (int i = threadIdx.x; i < nr * K; i += M) {
        int r = i / K, k = i - r * K;
        float v = EMB ? X[(size_t)ids[row0 + r] * K + k]
                      : X[(size_t)row0 * K + i];
        sxt[k * PAD + r] = v;
    }
    for (int i = threadIdx.x; i < (ROWS - nr) * K; i += M) {
        int r = nr + i / K, k = i - (i / K) * K;
        sxt[k * PAD + r] = 0.0f;
    }
    __syncthreads();

    int c = threadIdx.x;
    ull al[NP], ar[NP];
    {
        ull bl2 = pack2(bl[c], bl[c]);
        ull br2 = pack2(br[c], br[c]);
        #pragma unroll
        for (int p = 0; p < NP; p++) { al[p] = bl2; ar[p] = br2; }
    }
    #pragma unroll 4
    for (int k = 0; k < K; k++) {
        float wl = Wl[k * M + c], wr = Wr[k * M + c];
        ull wl2 = pack2(wl, wl), wr2 = pack2(wr, wr);
        const float* rowp = &sxt[k * PAD];
        #pragma unroll
        for (int p = 0; p < NP; p++) {
            ull xv = *(const ull*)(rowp + 2 * p);
            fma2(al[p], xv, wl2);
            fma2(ar[p], xv, wr2);
        }
    }
    #pragma unroll
    for (int p = 0; p < NP; p++) {
        float2 ul = *(float2*)&al[p];
        float2 ur = *(float2*)&ar[p];
        int r0 = 2 * p;
        if (r0 < nr) {
            Yl[(size_t)(row0 + r0) * M + c] = ul.x;
            Yr[(size_t)(row0 + r0) * M + c] = ur.x;
        }
        if (r0 + 1 < nr) {
            Yl[(size_t)(row0 + r0 + 1) * M + c] = ul.y;
            Yr[(size_t)(row0 + r0 + 1) * M + c] = ur.y;
        }
    }
}

// ---------------- warp-per-node fused attention (register-resident) -------------
// One warp owns one dst node: gather xl row into regs, warp-reduced logits,
// uniform-register online softmax, accumulate from the same regs.
// No shared memory, no block barriers, no global scratch. Any degree.
template <int H, int C>
__global__ void k_attnw(const float* __restrict__ xl, const float* __restrict__ xr,
                        const float* __restrict__ att, const float* __restrict__ bo,
                        const int* __restrict__ rp, const int* __restrict__ csrc,
                        float* __restrict__ out) {
    constexpr int M   = H * C;
    constexpr int R   = M / 32;     // regs per lane
    constexpr int RPH = C / 32;     // regs per head
    int warp = (blockIdx.x * blockDim.x + threadIdx.x) >> 5;
    int lane = threadIdx.x & 31;
    if (warp >= N_NODES) return;
    int dst = warp;
    int start = rp[dst];
    int deg   = rp[dst + 1] - start;

    float v_att[R], v_xr[R], acc[R];
    #pragma unroll
    for (int k = 0; k < R; k++) {
        int j = k * 32 + lane;
        v_att[k] = att[j];
        v_xr[k]  = xr[(size_t)dst * M + j];
        acc[k]   = 0.f;
    }
    float m[H], den[H];
    #pragma unroll
    for (int h = 0; h < H; h++) { m[h] = -INFINITY; den[h] = 0.f; }

    for (int base = 0; base < deg; base += 32) {
        int nn = min(32, deg - base);
        int myidx = (base + lane < deg) ? csrc[start + base + lane] : 0;
        for (int e = 0; e < nn; e++) {
            int src = __shfl_sync(0xffffffffu, myidx, e);
            const float* row = xl + (size_t)src * M;
            float x[R], s[H];
            #pragma unroll
            for (int h = 0; h < H; h++) s[h] = 0.f;
            #pragma unroll
            for (int k = 0; k < R; k++) {
                x[k] = row[k * 32 + lane];
                float u = x[k] + v_xr[k];
                u = (u > 0.f) ? u : 0.2f * u;
                s[k / RPH] = fmaf(v_att[k], u, s[k / RPH]);
            }
            #pragma unroll
            for (int h = 0; h < H; h++) {
                #pragma unroll
                for (int o = 16; o; o >>= 1)
                    s[h] += __shfl_xor_sync(0xffffffffu, s[h], o);
            }
            float sc[H], pe[H];
            #pragma unroll
            for (int h = 0; h < H; h++) {
                float mn = fmaxf(m[h], s[h]);
                sc[h] = __expf(m[h] - mn);     // exp(-inf)=0 on first edge
                pe[h] = __expf(s[h] - mn);
                den[h] = den[h] * sc[h] + pe[h];
                m[h] = mn;
            }
            #pragma unroll
            for (int k = 0; k < R; k++) {
                int h = k / RPH;
                acc[k] = fmaf(acc[k], sc[h], pe[h] * x[k]);
            }
        }
    }

    #pragma unroll
    for (int k = 0; k < R; k++) {
        int j = k * 32 + lane;
        out[(size_t)dst * M + j] = __fdividef(acc[k], den[k / RPH]) + bo[j];
    }
}

// ---------------- pooling (sorted batch -> run-length local sums) ---------------
__global__ void k_pool2(const float* __restrict__ x, const int* __restrict__ batch,
                        float* __restrict__ gs, float* __restrict__ cnt) {
    int j = threadIdx.x;              // 0..63 feature
    int w = threadIdx.y;              // 0..3
    int i0 = blockIdx.x * 128;
    int iend = min(i0 + 128, N_NODES);
    float acc = 0.f, cn = 0.f;
    int curb = -1;
    for (int i = i0 + w; i < iend; i += 4) {
        int b = batch[i];
        if (b != curb) {
            if (curb >= 0) {
                atomicAdd(&gs[curb * 64 + j], acc);
                if (j == 0) atomicAdd(&cnt[curb], cn);
            }
            curb = b; acc = 0.f; cn = 0.f;
        }
        acc += x[(size_t)i * 64 + j];
        cn += 1.f;
    }
    if (curb >= 0) {
        atomicAdd(&gs[curb * 64 + j], acc);
        if (j == 0) atomicAdd(&cnt[curb], cn);
    }
}

__global__ void k_mlp(const float* __restrict__ gs, const float* __restrict__ cnt,
                      const float* __restrict__ demo,
                      const float* __restrict__ Wc1, const float* __restrict__ bc1,
                      const float* __restrict__ Wc2, const float* __restrict__ bc2,
                      float* __restrict__ out) {
    int g = blockIdx.x * blockDim.x + threadIdx.x;
    if (g >= G_GRAPHS) return;
    float inv = 1.0f / fmaxf(cnt[g], 1.0f);
    float in[69];
    #pragma unroll
    for (int j = 0; j < 64; j++) in[j] = gs[g * 64 + j] * inv;
    #pragma unroll
    for (int j = 0; j < 5; j++) in[64 + j] = demo[g * 5 + j];
    float h[32];
    #pragma unroll
    for (int o = 0; o < 32; o++) {
        float a = bc1[o];
        for (int i = 0; i < 69; i++) a = fmaf(in[i], Wc1[i * 32 + o], a);
        h[o] = fmaxf(a, 0.0f);
    }
    #pragma unroll
    for (int o = 0; o < 2; o++) {
        float a = bc2[o];
        #pragma unroll
        for (int i = 0; i < 32; i++) a = fmaf(h[i], Wc2[i * 2 + o], a);
        out[g * 2 + o] = a;
    }
}

// ---------------- launch --------------------------------------------------------
static inline int ceil_div(int a, int b) { return (a + b - 1) / b; }

extern "C" void kernel_launch(void* const* d_in, const int* in_sizes, int n_in,
                              void* d_out, int out_size) {
    const float* emb  = (const float*)d_in[0];
    const float* Wl0  = (const float*)d_in[1];
    const float* bl0  = (const float*)d_in[2];
    const float* Wr0  = (const float*)d_in[3];
    const float* br0  = (const float*)d_in[4];
    const float* att0 = (const float*)d_in[5];
    const float* bo0  = (const float*)d_in[6];
    const float* Wl1  = (const float*)d_in[7];
    const float* bl1  = (const float*)d_in[8];
    const float* Wr1  = (const float*)d_in[9];
    const float* br1  = (const float*)d_in[10];
    const float* att1 = (const float*)d_in[11];
    const float* bo1  = (const float*)d_in[12];
    const float* Wl2  = (const float*)d_in[13];
    const float* bl2  = (const float*)d_in[14];
    const float* Wr2  = (const float*)d_in[15];
    const float* br2  = (const float*)d_in[16];
    const float* att2 = (const float*)d_in[17];
    const float* bo2  = (const float*)d_in[18];
    const float* Wc1  = (const float*)d_in[19];
    const float* bc1  = (const float*)d_in[20];
    const float* Wc2  = (const float*)d_in[21];
    const float* bc2  = (const float*)d_in[22];
    const float* demo = (const float*)d_in[23];
    const int*   ids  = (const int*)d_in[24];
    const int*   ei   = (const int*)d_in[25];
    const int*   batch= (const int*)d_in[26];
    float* out = (float*)d_out;

    float *px, *pxl, *pxr, *pgs, *pcnt;
    int *pdeg, *prp, *pcur, *pcsrc, *ppart;
    cudaGetSymbolAddress((void**)&px,    g_x);
    cudaGetSymbolAddress((void**)&pxl,   g_xl);
    cudaGetSymbolAddress((void**)&pxr,   g_xr);
    cudaGetSymbolAddress((void**)&pdeg,  g_deg);
    cudaGetSymbolAddress((void**)&prp,   g_rp);
    cudaGetSymbolAddress((void**)&pcur,  g_cur);
    cudaGetSymbolAddress((void**)&pcsrc, g_csrc);
    cudaGetSymbolAddress((void**)&ppart, g_part);
    cudaGetSymbolAddress((void**)&pgs,   g_gs);
    cudaGetSymbolAddress((void**)&pcnt,  g_cnt);

    const int T = 256;
    const int WARPS_PER_BLOCK = 8;                       // 256 threads
    const int ATT_GRID = ceil_div(N_NODES, WARPS_PER_BLOCK);

    // CSR by destination (shared by all three layers)
    k_fill_i<<<ceil_div(N_NODES, T), T>>>(pdeg, 0, N_NODES);
    k_count<<<ceil_div(E_TOT, T), T>>>(ei, pdeg);
    k_scan1<<<SCAN_NB, SCAN_B>>>(pdeg, ppart);
    k_scan2<<<1, 1>>>(ppart);
    k_scan3<<<SCAN_NB, SCAN_B>>>(pdeg, ppart, prp, pcur);
    k_scatter<<<ceil_div(E_TOT, T), T>>>(ei, pcur, pcsrc);

    // layer 0: emb-gathered 16 -> 3 heads x 32   (embedding lookup fused)
    k_gemm2<16, 96, 32, true><<<ceil_div(N_NODES, 32), 96>>>(emb, ids, Wl0, bl0, Wr0, br0, pxl, pxr);
    k_attnw<3, 32><<<ATT_GRID, T>>>(pxl, pxr, att0, bo0, prp, pcsrc, px);

    // layer 1: 96 -> 2 heads x 96
    k_gemm2<96, 192, 32, false><<<ceil_div(N_NODES, 32), 192>>>(px, nullptr, Wl1, bl1, Wr1, br1, pxl, pxr);
    k_attnw<2, 96><<<ATT_GRID, T>>>(pxl, pxr, att1, bo1, prp, pcsrc, px);

    // layer 2: 192 -> 1 head x 64
    k_gemm2<192, 64, 32, false><<<ceil_div(N_NODES, 32), 64>>>(px, nullptr, Wl2, bl2, Wr2, br2, pxl, pxr);
    k_attnw<1, 64><<<ATT_GRID, T>>>(pxl, pxr, att2, bo2, prp, pcsrc, px);

    // global mean pool + MLP head
    k_fill_f<<<ceil_div(G_GRAPHS * 64, T), T>>>(pgs, 0.0f, G_GRAPHS * 64);
    k_fill_f<<<1, G_GRAPHS>>>(pcnt, 0.0f, G_GRAPHS);
    dim3 pb(64, 4);
    k_pool2<<<ceil_div(N_NODES, 128), pb>>>(px, batch, pgs, pcnt);
    k_mlp<<<1, G_GRAPHS>>>(pgs, pcnt, demo, Wc1, bc1, Wc2, bc2, out);
}